// round 3
// baseline (speedup 1.0000x reference)
#include <cuda_runtime.h>
#include <cstdint>

// Problem shape (fixed by the dataset): N=10000, E=160000, IN=OUT=512, TC=256.
#define MAXN   10240
#define DIMK   512
#define DIMOUT 512
#define DIMTC  256

// Static device scratch (no runtime allocation allowed).
__device__ float g_xw[MAXN * DIMOUT];   // x @ W
__device__ float g_dinv[MAXN];          // deg -> rsqrt(deg)
__device__ float g_tb[DIMOUT];          // b + bt + t_emb @ Wt

// ---------------------------------------------------------------------------
// K1: deg[i] = 1.0 (self loop)
// ---------------------------------------------------------------------------
__global__ void k_deg_init(float* deg, int N) {
    int i = blockIdx.x * blockDim.x + threadIdx.x;
    if (i < N) deg[i] = 1.0f;
}

// ---------------------------------------------------------------------------
// K2: time/bias vector  tb[j] = b[j] + bt[j] + sum_k t_emb[k]*Wt[k,j]
// ---------------------------------------------------------------------------
__global__ void k_time_bias(const float* __restrict__ t_emb,
                            const float* __restrict__ Wt,
                            const float* __restrict__ b,
                            const float* __restrict__ bt,
                            float* __restrict__ tb) {
    int j = threadIdx.x;
    float acc = b[j] + bt[j];
#pragma unroll 8
    for (int k = 0; k < DIMTC; k++) {
        acc += t_emb[k] * Wt[k * DIMOUT + j];
    }
    tb[j] = acc;
}

// ---------------------------------------------------------------------------
// K3: degree accumulation over edges (dst = ei[E + e]) — edge_index is INT32
// ---------------------------------------------------------------------------
__global__ void k_deg_edges(const int* __restrict__ ei, float* deg, int E) {
    int e = blockIdx.x * blockDim.x + threadIdx.x;
    if (e < E) {
        int d = ei[E + e];
        atomicAdd(&deg[d], 1.0f);
    }
}

// ---------------------------------------------------------------------------
// K4: dinv[i] = rsqrt(deg[i])
// ---------------------------------------------------------------------------
__global__ void k_rsqrt(float* deg, int N) {
    int i = blockIdx.x * blockDim.x + threadIdx.x;
    if (i < N) deg[i] = rsqrtf(deg[i]);
}

// ---------------------------------------------------------------------------
// K5: GEMM  C[N,512] = A[N,512] @ B[512,512]   (fp32, 64x64 tiles, BK=16)
// ---------------------------------------------------------------------------
__global__ __launch_bounds__(256) void k_gemm(const float* __restrict__ A,
                                              const float* __restrict__ B,
                                              float* __restrict__ C, int N) {
    constexpr int BM = 64, BN = 64, BK = 16;
    __shared__ float As[BK][BM];   // transposed store: As[k][m]
    __shared__ float Bs[BK][BN];

    int tid = threadIdx.x;
    int tx = tid & 15;
    int ty = tid >> 4;
    int rowBase = blockIdx.y * BM;
    int colBase = blockIdx.x * BN;

    int ar = tid >> 2;             // 0..63
    int ac = (tid & 3) * 4;        // 0,4,8,12
    int br = tid >> 4;             // 0..15
    int bc = (tid & 15) * 4;       // 0..60

    float acc[4][4];
#pragma unroll
    for (int i = 0; i < 4; i++)
#pragma unroll
        for (int j = 0; j < 4; j++) acc[i][j] = 0.0f;

    for (int k0 = 0; k0 < DIMK; k0 += BK) {
        int arow = rowBase + ar;
        float4 av = make_float4(0.f, 0.f, 0.f, 0.f);
        if (arow < N)
            av = *reinterpret_cast<const float4*>(&A[(size_t)arow * DIMK + k0 + ac]);
        As[ac + 0][ar] = av.x;
        As[ac + 1][ar] = av.y;
        As[ac + 2][ar] = av.z;
        As[ac + 3][ar] = av.w;

        float4 bv = *reinterpret_cast<const float4*>(
            &B[(size_t)(k0 + br) * DIMOUT + colBase + bc]);
        *reinterpret_cast<float4*>(&Bs[br][bc]) = bv;

        __syncthreads();

#pragma unroll
        for (int kk = 0; kk < BK; kk++) {
            float4 a4 = *reinterpret_cast<const float4*>(&As[kk][ty * 4]);
            float4 b4 = *reinterpret_cast<const float4*>(&Bs[kk][tx * 4]);
            float a[4] = {a4.x, a4.y, a4.z, a4.w};
            float b[4] = {b4.x, b4.y, b4.z, b4.w};
#pragma unroll
            for (int i = 0; i < 4; i++)
#pragma unroll
                for (int j = 0; j < 4; j++) acc[i][j] += a[i] * b[j];
        }
        __syncthreads();
    }

#pragma unroll
    for (int i = 0; i < 4; i++) {
        int r = rowBase + ty * 4 + i;
        if (r < N) {
            float4 v = make_float4(acc[i][0], acc[i][1], acc[i][2], acc[i][3]);
            *reinterpret_cast<float4*>(&C[(size_t)r * DIMOUT + colBase + tx * 4]) = v;
        }
    }
}

// ---------------------------------------------------------------------------
// K6: init out with self-loop + bias:  out[i,:] = tb + dinv[i]^2 * xw[i,:]
// ---------------------------------------------------------------------------
__global__ void k_init_out(const float* __restrict__ xw,
                           const float* __restrict__ dinv,
                           const float* __restrict__ tb,
                           float* __restrict__ out, int N) {
    unsigned idx = blockIdx.x * blockDim.x + threadIdx.x;
    unsigned i = idx >> 7;
    unsigned t = idx & 127;
    if (i >= (unsigned)N) return;
    float di = dinv[i];
    float w = di * di;
    float4 v = *(reinterpret_cast<const float4*>(xw + (size_t)i * DIMOUT) + t);
    float4 tb4 = *(reinterpret_cast<const float4*>(tb) + t);
    float4 o;
    o.x = tb4.x + w * v.x;
    o.y = tb4.y + w * v.y;
    o.z = tb4.z + w * v.z;
    o.w = tb4.w + w * v.w;
    *(reinterpret_cast<float4*>(out + (size_t)i * DIMOUT) + t) = o;
}

// ---------------------------------------------------------------------------
// K7: edge scatter:  out[dst,:] += dinv[src]*dinv[dst] * xw[src,:]
// 128 threads per edge (float4 lanes); 4 scalar REDs per lane (no return).
// ---------------------------------------------------------------------------
__global__ __launch_bounds__(512) void k_scatter(const int* __restrict__ ei,
                                                 const float* __restrict__ xw,
                                                 const float* __restrict__ dinv,
                                                 float* __restrict__ out, int E) {
    unsigned idx = blockIdx.x * blockDim.x + threadIdx.x;
    unsigned e = idx >> 7;
    unsigned t = idx & 127;
    if (e >= (unsigned)E) return;
    int s = __ldg(&ei[e]);
    int d = __ldg(&ei[E + e]);
    float w = __ldg(&dinv[s]) * __ldg(&dinv[d]);
    float4 v = __ldg(reinterpret_cast<const float4*>(xw + (size_t)s * DIMOUT) + t);
    float* p = out + (size_t)d * DIMOUT + t * 4;
    atomicAdd(p + 0, w * v.x);
    atomicAdd(p + 1, w * v.y);
    atomicAdd(p + 2, w * v.z);
    atomicAdd(p + 3, w * v.w);
}

// ---------------------------------------------------------------------------
// launch
// ---------------------------------------------------------------------------
extern "C" void kernel_launch(void* const* d_in, const int* in_sizes, int n_in,
                              void* d_out, int out_size) {
    const float* x    = (const float*)d_in[0];
    const float* temb = (const float*)d_in[1];
    const int*   ei   = (const int*)d_in[2];   // int32! (JAX x64 disabled)
    const float* W    = (const float*)d_in[3];
    const float* b    = (const float*)d_in[4];
    const float* Wt   = (const float*)d_in[5];
    const float* bt   = (const float*)d_in[6];
    float*       out  = (float*)d_out;

    int N = in_sizes[0] / DIMK;
    int E = in_sizes[2] / 2;

    float* xw;   cudaGetSymbolAddress((void**)&xw,   g_xw);
    float* dinv; cudaGetSymbolAddress((void**)&dinv, g_dinv);
    float* tb;   cudaGetSymbolAddress((void**)&tb,   g_tb);

    k_deg_init<<<(N + 255) / 256, 256>>>(dinv, N);
    k_time_bias<<<1, DIMOUT>>>(temb, Wt, b, bt, tb);
    k_deg_edges<<<(E + 255) / 256, 256>>>(ei, dinv, E);
    k_rsqrt<<<(N + 255) / 256, 256>>>(dinv, N);

    dim3 gg(DIMOUT / 64, (N + 63) / 64);
    k_gemm<<<gg, 256>>>(x, W, xw, N);

    unsigned initThreads = (unsigned)N * 128u;
    k_init_out<<<(initThreads + 255) / 256, 256>>>(xw, dinv, tb, out, N);

    unsigned scatThreads = (unsigned)E * 128u;
    k_scatter<<<(scatThreads + 511) / 512, 512>>>(ei, xw, dinv, out, E);
}

// round 7
// speedup vs baseline: 1.4480x; 1.4480x over previous
#include <cuda_runtime.h>
#include <cstdint>

// Problem shape (fixed by the dataset): N=10000, E=160000, IN=OUT=512, TC=256.
#define MAXN   10240
#define DIMK   512
#define DIMOUT 512
#define DIMTC  256

// Static device scratch (no runtime allocation allowed).
__device__ float g_xw[MAXN * DIMOUT];   // x @ W
__device__ float g_dinv[MAXN];          // deg -> rsqrt(deg)
__device__ float g_tb[DIMOUT];          // b + bt + t_emb @ Wt

// ---------------------------------------------------------------------------
// helpers
// ---------------------------------------------------------------------------
__device__ __forceinline__ float to_tf32(float x) {
    uint32_t u;
    asm("cvt.rna.tf32.f32 %0, %1;" : "=r"(u) : "f"(x));
    return __uint_as_float(u);
}

__device__ __forceinline__ void mma_tf32(float* d, const uint32_t* a, const uint32_t* b) {
    asm volatile(
        "mma.sync.aligned.m16n8k8.row.col.f32.tf32.tf32.f32 "
        "{%0,%1,%2,%3}, {%4,%5,%6,%7}, {%8,%9}, {%0,%1,%2,%3};"
        : "+f"(d[0]), "+f"(d[1]), "+f"(d[2]), "+f"(d[3])
        : "r"(a[0]), "r"(a[1]), "r"(a[2]), "r"(a[3]),
          "r"(b[0]), "r"(b[1]));
}

// ---------------------------------------------------------------------------
// K1: deg[i] = 1.0 (self loop)
// ---------------------------------------------------------------------------
__global__ void k_deg_init(float* deg, int N) {
    int i = blockIdx.x * blockDim.x + threadIdx.x;
    if (i < N) deg[i] = 1.0f;
}

// ---------------------------------------------------------------------------
// K2: tb[j] = b[j] + bt[j] + sum_k t_emb[k]*Wt[k,j]
// grid 16 x 256 threads; block handles 32 cols, 8 k-chunks reduced in smem
// ---------------------------------------------------------------------------
__global__ void k_time_bias(const float* __restrict__ t_emb,
                            const float* __restrict__ Wt,
                            const float* __restrict__ b,
                            const float* __restrict__ bt,
                            float* __restrict__ tb) {
    __shared__ float red[8][32];
    int jloc = threadIdx.x & 31;
    int kc   = threadIdx.x >> 5;       // 0..7
    int j    = blockIdx.x * 32 + jloc;
    float acc = 0.0f;
    int k0 = kc * 32;
#pragma unroll
    for (int k = 0; k < 32; k++) {
        acc += t_emb[k0 + k] * Wt[(k0 + k) * DIMOUT + j];
    }
    red[kc][jloc] = acc;
    __syncthreads();
    if (kc == 0) {
        float s = b[j] + bt[j];
#pragma unroll
        for (int q = 0; q < 8; q++) s += red[q][jloc];
        tb[j] = s;
    }
}

// ---------------------------------------------------------------------------
// K3: degree accumulation over edges (dst = ei[E + e]) — edge_index is INT32
// ---------------------------------------------------------------------------
__global__ void k_deg_edges(const int* __restrict__ ei, float* deg, int E) {
    int e = blockIdx.x * blockDim.x + threadIdx.x;
    if (e < E) {
        int d = ei[E + e];
        atomicAdd(&deg[d], 1.0f);
    }
}

// ---------------------------------------------------------------------------
// K4: dinv[i] = rsqrt(deg[i])
// ---------------------------------------------------------------------------
__global__ void k_rsqrt(float* deg, int N) {
    int i = blockIdx.x * blockDim.x + threadIdx.x;
    if (i < N) deg[i] = rsqrtf(deg[i]);
}

// ---------------------------------------------------------------------------
// K5: TF32 tensor-core GEMM  C[N,512] = A[N,512] @ B[512,512]
// 128x128 block tile, 8 warps of 64x32, BK=32, m16n8k8 mma.sync
// SMEM: As[m][k] stride 36 (conflict-free frag LDS: bank=4g+c),
//       Bs[k][n] stride 136 (bank=8c+g)
// ---------------------------------------------------------------------------
__global__ __launch_bounds__(256) void k_gemm_tf32(const float* __restrict__ A,
                                                   const float* __restrict__ B,
                                                   float* __restrict__ C, int N) {
    __shared__ float As[128 * 36];
    __shared__ float Bs[32 * 136];

    int tid  = threadIdx.x;
    int lane = tid & 31;
    int wid  = tid >> 5;
    int wm   = wid & 1;       // 0..1 -> 64-row half
    int wn   = wid >> 1;      // 0..3 -> 32-col slice
    int g    = lane >> 2;     // 0..7
    int c    = lane & 3;      // 0..3

    int rowBase = blockIdx.y * 128;
    int colBase = blockIdx.x * 128;

    float acc[4][4][4];
#pragma unroll
    for (int mt = 0; mt < 4; mt++)
#pragma unroll
        for (int nt = 0; nt < 4; nt++)
#pragma unroll
            for (int q = 0; q < 4; q++) acc[mt][nt][q] = 0.0f;

    int ar  = tid >> 3;        // 0..31 (row group for A loads)
    int ac4 = tid & 7;         // float4 index within 32-col row
    int bkr = tid >> 5;        // 0..7  (k row group for B loads)
    int bc4 = tid & 31;        // float4 index within 128-col row

    for (int k0 = 0; k0 < DIMK; k0 += 32) {
        // A tile: 128 rows x 32 cols, coalesced, tf32-rounded
#pragma unroll
        for (int j = 0; j < 4; j++) {
            int row  = ar + 32 * j;
            int grow = rowBase + row;
            float4 v = make_float4(0.f, 0.f, 0.f, 0.f);
            if (grow < N)
                v = *reinterpret_cast<const float4*>(&A[(size_t)grow * DIMK + k0 + ac4 * 4]);
            v.x = to_tf32(v.x); v.y = to_tf32(v.y);
            v.z = to_tf32(v.z); v.w = to_tf32(v.w);
            *reinterpret_cast<float4*>(&As[row * 36 + ac4 * 4]) = v;
        }
        // B tile: 32 rows x 128 cols, coalesced, tf32-rounded
#pragma unroll
        for (int j = 0; j < 4; j++) {
            int k = bkr + 8 * j;
            float4 v = *reinterpret_cast<const float4*>(
                &B[(size_t)(k0 + k) * DIMOUT + colBase + bc4 * 4]);
            v.x = to_tf32(v.x); v.y = to_tf32(v.y);
            v.z = to_tf32(v.z); v.w = to_tf32(v.w);
            *reinterpret_cast<float4*>(&Bs[k * 136 + bc4 * 4]) = v;
        }
        __syncthreads();

#pragma unroll
        for (int kk = 0; kk < 32; kk += 8) {
            uint32_t afr[4][4];
            uint32_t bfr[4][2];
#pragma unroll
            for (int mt = 0; mt < 4; mt++) {
                int rb = wm * 64 + mt * 16;
                afr[mt][0] = __float_as_uint(As[(rb + g)     * 36 + kk + c]);
                afr[mt][1] = __float_as_uint(As[(rb + g + 8) * 36 + kk + c]);
                afr[mt][2] = __float_as_uint(As[(rb + g)     * 36 + kk + c + 4]);
                afr[mt][3] = __float_as_uint(As[(rb + g + 8) * 36 + kk + c + 4]);
            }
#pragma unroll
            for (int nt = 0; nt < 4; nt++) {
                int nb = wn * 32 + nt * 8;
                bfr[nt][0] = __float_as_uint(Bs[(kk + c)     * 136 + nb + g]);
                bfr[nt][1] = __float_as_uint(Bs[(kk + c + 4) * 136 + nb + g]);
            }
#pragma unroll
            for (int mt = 0; mt < 4; mt++)
#pragma unroll
                for (int nt = 0; nt < 4; nt++)
                    mma_tf32(acc[mt][nt], afr[mt], bfr[nt]);
        }
        __syncthreads();
    }

    // epilogue: c0,c1 at (row, 2c), c2,c3 at (row+8, 2c)
#pragma unroll
    for (int mt = 0; mt < 4; mt++) {
        int row = rowBase + wm * 64 + mt * 16 + g;
#pragma unroll
        for (int nt = 0; nt < 4; nt++) {
            int col = colBase + wn * 32 + nt * 8 + 2 * c;
            if (row < N)
                *reinterpret_cast<float2*>(&C[(size_t)row * DIMOUT + col]) =
                    make_float2(acc[mt][nt][0], acc[mt][nt][1]);
            if (row + 8 < N)
                *reinterpret_cast<float2*>(&C[(size_t)(row + 8) * DIMOUT + col]) =
                    make_float2(acc[mt][nt][2], acc[mt][nt][3]);
        }
    }
}

// ---------------------------------------------------------------------------
// K6: init out with self-loop + bias:  out[i,:] = tb + dinv[i]^2 * xw[i,:]
// ---------------------------------------------------------------------------
__global__ void k_init_out(const float* __restrict__ xw,
                           const float* __restrict__ dinv,
                           const float* __restrict__ tb,
                           float* __restrict__ out, int N) {
    unsigned idx = blockIdx.x * blockDim.x + threadIdx.x;
    unsigned i = idx >> 7;
    unsigned t = idx & 127;
    if (i >= (unsigned)N) return;
    float di = dinv[i];
    float w = di * di;
    float4 v = *(reinterpret_cast<const float4*>(xw + (size_t)i * DIMOUT) + t);
    float4 tb4 = *(reinterpret_cast<const float4*>(tb) + t);
    float4 o;
    o.x = tb4.x + w * v.x;
    o.y = tb4.y + w * v.y;
    o.z = tb4.z + w * v.z;
    o.w = tb4.w + w * v.w;
    *(reinterpret_cast<float4*>(out + (size_t)i * DIMOUT) + t) = o;
}

// ---------------------------------------------------------------------------
// K7: edge scatter:  out[dst,:] += dinv[src]*dinv[dst] * xw[src,:]
// ---------------------------------------------------------------------------
__global__ __launch_bounds__(512) void k_scatter(const int* __restrict__ ei,
                                                 const float* __restrict__ xw,
                                                 const float* __restrict__ dinv,
                                                 float* __restrict__ out, int E) {
    unsigned idx = blockIdx.x * blockDim.x + threadIdx.x;
    unsigned e = idx >> 7;
    unsigned t = idx & 127;
    if (e >= (unsigned)E) return;
    int s = __ldg(&ei[e]);
    int d = __ldg(&ei[E + e]);
    float w = __ldg(&dinv[s]) * __ldg(&dinv[d]);
    float4 v = __ldg(reinterpret_cast<const float4*>(xw + (size_t)s * DIMOUT) + t);
    float* p = out + (size_t)d * DIMOUT + t * 4;
    atomicAdd(p + 0, w * v.x);
    atomicAdd(p + 1, w * v.y);
    atomicAdd(p + 2, w * v.z);
    atomicAdd(p + 3, w * v.w);
}

// ---------------------------------------------------------------------------
// launch
// ---------------------------------------------------------------------------
extern "C" void kernel_launch(void* const* d_in, const int* in_sizes, int n_in,
                              void* d_out, int out_size) {
    const float* x    = (const float*)d_in[0];
    const float* temb = (const float*)d_in[1];
    const int*   ei   = (const int*)d_in[2];   // int32 (JAX x64 disabled)
    const float* W    = (const float*)d_in[3];
    const float* b    = (const float*)d_in[4];
    const float* Wt   = (const float*)d_in[5];
    const float* bt   = (const float*)d_in[6];
    float*       out  = (float*)d_out;

    int N = in_sizes[0] / DIMK;
    int E = in_sizes[2] / 2;

    float* xw;   cudaGetSymbolAddress((void**)&xw,   g_xw);
    float* dinv; cudaGetSymbolAddress((void**)&dinv, g_dinv);
    float* tb;   cudaGetSymbolAddress((void**)&tb,   g_tb);

    k_deg_init<<<(N + 255) / 256, 256>>>(dinv, N);
    k_time_bias<<<DIMOUT / 32, 256>>>(temb, Wt, b, bt, tb);
    k_deg_edges<<<(E + 255) / 256, 256>>>(ei, dinv, E);
    k_rsqrt<<<(N + 255) / 256, 256>>>(dinv, N);

    dim3 gg(DIMOUT / 128, (N + 127) / 128);
    k_gemm_tf32<<<gg, 256>>>(x, W, xw, N);

    unsigned initThreads = (unsigned)N * 128u;
    k_init_out<<<(initThreads + 255) / 256, 256>>>(xw, dinv, tb, out, N);

    unsigned scatThreads = (unsigned)E * 128u;
    k_scatter<<<(scatThreads + 511) / 512, 512>>>(ei, xw, dinv, out, E);
}

// round 9
// speedup vs baseline: 3.4153x; 2.3587x over previous
#include <cuda_runtime.h>
#include <cstdint>

// Problem shape (fixed by the dataset): N=10000, E=160000, IN=OUT=512, TC=256.
#define MAXN   10240
#define MAXE   163840
#define DIMK   512
#define DIMOUT 512
#define DIMTC  256

// Static device scratch (no runtime allocation allowed).
__device__ float g_xw[MAXN * DIMOUT];   // x @ W
__device__ float g_dinv[MAXN];          // rsqrt(deg)
__device__ float g_tb[DIMOUT];          // b + bt + t_emb @ Wt
__device__ int   g_count[MAXN];         // in-degree (excl self loop)
__device__ int   g_rowstart[MAXN + 1];  // CSR row offsets
__device__ int   g_cursor[MAXN];        // fill cursors
__device__ int   g_csr_src[MAXE];       // src node per CSR slot

// ---------------------------------------------------------------------------
// helpers
// ---------------------------------------------------------------------------
__device__ __forceinline__ float to_tf32(float x) {
    uint32_t u;
    asm("cvt.rna.tf32.f32 %0, %1;" : "=r"(u) : "f"(x));
    return __uint_as_float(u);
}

__device__ __forceinline__ void mma_tf32(float* d, const uint32_t* a, const uint32_t* b) {
    asm volatile(
        "mma.sync.aligned.m16n8k8.row.col.f32.tf32.tf32.f32 "
        "{%0,%1,%2,%3}, {%4,%5,%6,%7}, {%8,%9}, {%0,%1,%2,%3};"
        : "+f"(d[0]), "+f"(d[1]), "+f"(d[2]), "+f"(d[3])
        : "r"(a[0]), "r"(a[1]), "r"(a[2]), "r"(a[3]),
          "r"(b[0]), "r"(b[1]));
}

// ---------------------------------------------------------------------------
// K1: count[i] = 0
// ---------------------------------------------------------------------------
__global__ void k_zero_count(int* count, int N) {
    int i = blockIdx.x * blockDim.x + threadIdx.x;
    if (i < N) count[i] = 0;
}

// ---------------------------------------------------------------------------
// K2: histogram of dst (edge_index is INT32: src=[0,E), dst=[E,2E))
// ---------------------------------------------------------------------------
__global__ void k_count_edges(const int* __restrict__ ei, int* count, int E) {
    int e = blockIdx.x * blockDim.x + threadIdx.x;
    if (e < E) atomicAdd(&count[ei[E + e]], 1);
}

// ---------------------------------------------------------------------------
// K3: exclusive scan of count -> rowstart[0..N], plus cursor copy
// one block, 1024 threads, each owns a contiguous chunk
// ---------------------------------------------------------------------------
__global__ __launch_bounds__(1024) void k_scan(const int* __restrict__ count,
                                               int* __restrict__ rowstart,
                                               int* __restrict__ cursor, int N) {
    __shared__ int part[1024];
    int tid = threadIdx.x;
    int PER = (N + 1023) >> 10;
    int base = tid * PER;
    int s = 0;
    for (int q = 0; q < PER; q++) {
        int idx = base + q;
        s += (idx < N) ? count[idx] : 0;
    }
    part[tid] = s;
    __syncthreads();
    // inclusive Hillis-Steele scan over 1024 partials
    for (int off = 1; off < 1024; off <<= 1) {
        int v = (tid >= off) ? part[tid - off] : 0;
        __syncthreads();
        part[tid] += v;
        __syncthreads();
    }
    int run = (tid > 0) ? part[tid - 1] : 0;
    for (int q = 0; q < PER; q++) {
        int idx = base + q;
        if (idx <= N) {
            rowstart[idx] = run;
            if (idx < N) cursor[idx] = run;
        }
        if (idx < N) run += count[idx];
    }
}

// ---------------------------------------------------------------------------
// K4: dinv[i] = rsqrt(count[i] + 1)   (self loop)
// ---------------------------------------------------------------------------
__global__ void k_dinv(const int* __restrict__ count, float* dinv, int N) {
    int i = blockIdx.x * blockDim.x + threadIdx.x;
    if (i < N) dinv[i] = rsqrtf((float)count[i] + 1.0f);
}

// ---------------------------------------------------------------------------
// K5: CSR fill: csr_src[pos] = src, pos = cursor[dst]++
// ---------------------------------------------------------------------------
__global__ void k_fill(const int* __restrict__ ei, int* cursor,
                       int* __restrict__ csr_src, int E) {
    int e = blockIdx.x * blockDim.x + threadIdx.x;
    if (e < E) {
        int s = ei[e];
        int d = ei[E + e];
        int pos = atomicAdd(&cursor[d], 1);
        csr_src[pos] = s;
    }
}

// ---------------------------------------------------------------------------
// K6: tb[j] = b[j] + bt[j] + sum_k t_emb[k]*Wt[k,j]
// ---------------------------------------------------------------------------
__global__ void k_time_bias(const float* __restrict__ t_emb,
                            const float* __restrict__ Wt,
                            const float* __restrict__ b,
                            const float* __restrict__ bt,
                            float* __restrict__ tb) {
    __shared__ float red[8][32];
    int jloc = threadIdx.x & 31;
    int kc   = threadIdx.x >> 5;
    int j    = blockIdx.x * 32 + jloc;
    float acc = 0.0f;
    int k0 = kc * 32;
#pragma unroll
    for (int k = 0; k < 32; k++) {
        acc += t_emb[k0 + k] * Wt[(k0 + k) * DIMOUT + j];
    }
    red[kc][jloc] = acc;
    __syncthreads();
    if (kc == 0) {
        float s = b[j] + bt[j];
#pragma unroll
        for (int q = 0; q < 8; q++) s += red[q][jloc];
        tb[j] = s;
    }
}

// ---------------------------------------------------------------------------
// K7: TF32 tensor-core GEMM  C[N,512] = A[N,512] @ B[512,512]
// 128x128 block tile, 8 warps of 64x32, BK=32, m16n8k8 mma.sync
// ---------------------------------------------------------------------------
__global__ __launch_bounds__(256) void k_gemm_tf32(const float* __restrict__ A,
                                                   const float* __restrict__ B,
                                                   float* __restrict__ C, int N) {
    __shared__ float As[128 * 36];
    __shared__ float Bs[32 * 136];

    int tid  = threadIdx.x;
    int lane = tid & 31;
    int wid  = tid >> 5;
    int wm   = wid & 1;
    int wn   = wid >> 1;
    int g    = lane >> 2;
    int c    = lane & 3;

    int rowBase = blockIdx.y * 128;
    int colBase = blockIdx.x * 128;

    float acc[4][4][4];
#pragma unroll
    for (int mt = 0; mt < 4; mt++)
#pragma unroll
        for (int nt = 0; nt < 4; nt++)
#pragma unroll
            for (int q = 0; q < 4; q++) acc[mt][nt][q] = 0.0f;

    int ar  = tid >> 3;
    int ac4 = tid & 7;
    int bkr = tid >> 5;
    int bc4 = tid & 31;

    for (int k0 = 0; k0 < DIMK; k0 += 32) {
#pragma unroll
        for (int j = 0; j < 4; j++) {
            int row  = ar + 32 * j;
            int grow = rowBase + row;
            float4 v = make_float4(0.f, 0.f, 0.f, 0.f);
            if (grow < N)
                v = *reinterpret_cast<const float4*>(&A[(size_t)grow * DIMK + k0 + ac4 * 4]);
            v.x = to_tf32(v.x); v.y = to_tf32(v.y);
            v.z = to_tf32(v.z); v.w = to_tf32(v.w);
            *reinterpret_cast<float4*>(&As[row * 36 + ac4 * 4]) = v;
        }
#pragma unroll
        for (int j = 0; j < 4; j++) {
            int k = bkr + 8 * j;
            float4 v = *reinterpret_cast<const float4*>(
                &B[(size_t)(k0 + k) * DIMOUT + colBase + bc4 * 4]);
            v.x = to_tf32(v.x); v.y = to_tf32(v.y);
            v.z = to_tf32(v.z); v.w = to_tf32(v.w);
            *reinterpret_cast<float4*>(&Bs[k * 136 + bc4 * 4]) = v;
        }
        __syncthreads();

#pragma unroll
        for (int kk = 0; kk < 32; kk += 8) {
            uint32_t afr[4][4];
            uint32_t bfr[4][2];
#pragma unroll
            for (int mt = 0; mt < 4; mt++) {
                int rb = wm * 64 + mt * 16;
                afr[mt][0] = __float_as_uint(As[(rb + g)     * 36 + kk + c]);
                afr[mt][1] = __float_as_uint(As[(rb + g + 8) * 36 + kk + c]);
                afr[mt][2] = __float_as_uint(As[(rb + g)     * 36 + kk + c + 4]);
                afr[mt][3] = __float_as_uint(As[(rb + g + 8) * 36 + kk + c + 4]);
            }
#pragma unroll
            for (int nt = 0; nt < 4; nt++) {
                int nb = wn * 32 + nt * 8;
                bfr[nt][0] = __float_as_uint(Bs[(kk + c)     * 136 + nb + g]);
                bfr[nt][1] = __float_as_uint(Bs[(kk + c + 4) * 136 + nb + g]);
            }
#pragma unroll
            for (int mt = 0; mt < 4; mt++)
#pragma unroll
                for (int nt = 0; nt < 4; nt++)
                    mma_tf32(acc[mt][nt], afr[mt], bfr[nt]);
        }
        __syncthreads();
    }

#pragma unroll
    for (int mt = 0; mt < 4; mt++) {
        int row = rowBase + wm * 64 + mt * 16 + g;
#pragma unroll
        for (int nt = 0; nt < 4; nt++) {
            int col = colBase + wn * 32 + nt * 8 + 2 * c;
            if (row < N)
                *reinterpret_cast<float2*>(&C[(size_t)row * DIMOUT + col]) =
                    make_float2(acc[mt][nt][0], acc[mt][nt][1]);
            if (row + 8 < N)
                *reinterpret_cast<float2*>(&C[(size_t)(row + 8) * DIMOUT + col]) =
                    make_float2(acc[mt][nt][2], acc[mt][nt][3]);
        }
    }
}

// ---------------------------------------------------------------------------
// K8: CSR gather (atomic-free) — fuses self-loop + time bias:
//   out[i,:] = tb + dinv[i]^2 * xw[i,:] + sum_e dinv[i]*dinv[src_e]*xw[src_e,:]
// block = 128 threads (one float4 lane each), grid = N
// ---------------------------------------------------------------------------
__global__ __launch_bounds__(128) void k_gather(const int* __restrict__ rowstart,
                                                const int* __restrict__ csr_src,
                                                const float* __restrict__ xw,
                                                const float* __restrict__ dinv,
                                                const float* __restrict__ tb,
                                                float* __restrict__ out, int N) {
    int i = blockIdx.x;
    int t = threadIdx.x;
    int start = rowstart[i];
    int end   = rowstart[i + 1];
    float di  = dinv[i];

    float4 acc = *(reinterpret_cast<const float4*>(tb) + t);
    float4 v0  = __ldg(reinterpret_cast<const float4*>(xw + (size_t)i * DIMOUT) + t);
    float wsel = di * di;
    acc.x += wsel * v0.x;
    acc.y += wsel * v0.y;
    acc.z += wsel * v0.z;
    acc.w += wsel * v0.w;

    for (int j = start; j < end; j++) {
        int s   = __ldg(&csr_src[j]);
        float w = di * __ldg(&dinv[s]);
        float4 v = __ldg(reinterpret_cast<const float4*>(xw + (size_t)s * DIMOUT) + t);
        acc.x += w * v.x;
        acc.y += w * v.y;
        acc.z += w * v.z;
        acc.w += w * v.w;
    }
    *(reinterpret_cast<float4*>(out + (size_t)i * DIMOUT) + t) = acc;
}

// ---------------------------------------------------------------------------
// launch
// ---------------------------------------------------------------------------
extern "C" void kernel_launch(void* const* d_in, const int* in_sizes, int n_in,
                              void* d_out, int out_size) {
    const float* x    = (const float*)d_in[0];
    const float* temb = (const float*)d_in[1];
    const int*   ei   = (const int*)d_in[2];   // int32 (JAX x64 disabled)
    const float* W    = (const float*)d_in[3];
    const float* b    = (const float*)d_in[4];
    const float* Wt   = (const float*)d_in[5];
    const float* bt   = (const float*)d_in[6];
    float*       out  = (float*)d_out;

    int N = in_sizes[0] / DIMK;
    int E = in_sizes[2] / 2;

    float* xw;    cudaGetSymbolAddress((void**)&xw,    g_xw);
    float* dinv;  cudaGetSymbolAddress((void**)&dinv,  g_dinv);
    float* tb;    cudaGetSymbolAddress((void**)&tb,    g_tb);
    int* count;   cudaGetSymbolAddress((void**)&count, g_count);
    int* rowst;   cudaGetSymbolAddress((void**)&rowst, g_rowstart);
    int* cursor;  cudaGetSymbolAddress((void**)&cursor,g_cursor);
    int* csrsrc;  cudaGetSymbolAddress((void**)&csrsrc,g_csr_src);

    // CSR build + norms
    k_zero_count<<<(N + 255) / 256, 256>>>(count, N);
    k_count_edges<<<(E + 255) / 256, 256>>>(ei, count, E);
    k_scan<<<1, 1024>>>(count, rowst, cursor, N);
    k_dinv<<<(N + 255) / 256, 256>>>(count, dinv, N);
    k_fill<<<(E + 255) / 256, 256>>>(ei, cursor, csrsrc, E);

    // dense branches
    k_time_bias<<<DIMOUT / 32, 256>>>(temb, Wt, b, bt, tb);
    dim3 gg(DIMOUT / 128, (N + 127) / 128);
    k_gemm_tf32<<<gg, 256>>>(x, W, xw, N);

    // atomic-free aggregation (fuses init_out)
    k_gather<<<N, 128>>>(rowst, csrsrc, xw, dinv, tb, out, N);
}